// round 2
// baseline (speedup 1.0000x reference)
#include <cuda_runtime.h>
#include <cstdint>

// RationalsModel: out[i] = P(x[i]) / (|x[i] * Q(x[i])| + 1)
//   P = sum_{p=0}^{63} coef[p]      * x^p
//   Q = sum_{p=0}^{63} coef[64 + p] * x^p
//
// R2: FMA-pipe-bound (floor ~14.8us). R1 hit 62% fma pipe at occ=52.8%
// (46 regs -> 5 blocks/SM). Shrink to 4 elems/thread (2 f32x2 lanes),
// cap regs at 32 via launch_bounds -> 8 blocks/SM, 100% occupancy,
// 4 warps/SMSP to hide LDS latency and issue gaps.

__device__ __forceinline__ uint64_t pack2(float lo, float hi) {
    uint64_t r;
    asm("mov.b64 %0, {%1, %2};" : "=l"(r) : "f"(lo), "f"(hi));
    return r;
}

__device__ __forceinline__ void unpack2(uint64_t v, float& lo, float& hi) {
    asm("mov.b64 {%0, %1}, %2;" : "=f"(lo), "=f"(hi) : "l"(v));
}

// d = a * b + c  (packed 2x f32, rt_SMSP=2 for 2 scalar FMAs)
__device__ __forceinline__ uint64_t fma2(uint64_t a, uint64_t b, uint64_t c) {
    uint64_t d;
    asm("fma.rn.f32x2 %0, %1, %2, %3;" : "=l"(d) : "l"(a), "l"(b), "l"(c));
    return d;
}

static constexpr int THREADS = 256;
static constexpr int ELEMS_PER_THREAD = 4;                          // 2 f32x2 lanes
static constexpr int ELEMS_PER_BLOCK = THREADS * ELEMS_PER_THREAD;  // 1024
static constexpr int F4_PER_BLOCK = ELEMS_PER_BLOCK / 4;            // 256

__global__ __launch_bounds__(THREADS, 8)
void rational_kernel(const float4* __restrict__ x4,
                     const float* __restrict__ coef,
                     float4* __restrict__ out4)
{
    // Coefficients duplicated into both f32x2 halves: one ld.shared.b64
    // broadcast per polynomial per Horner step.
    __shared__ uint64_t sN[64];
    __shared__ uint64_t sM[64];

    int tid = threadIdx.x;
    if (tid < 128) {
        uint32_t u = __float_as_uint(coef[tid]);
        uint64_t p = (uint64_t)u | ((uint64_t)u << 32);
        if (tid < 64) sN[tid] = p;
        else          sM[tid - 64] = p;
    }
    __syncthreads();

    // One coalesced float4 load per thread.
    int base = blockIdx.x * F4_PER_BLOCK + tid;
    float4 a = x4[base];

    uint64_t xp[2];
    xp[0] = pack2(a.x, a.y);
    xp[1] = pack2(a.z, a.w);

    uint64_t accN[2], accD[2];
    {
        uint64_t n63 = sN[63];
        uint64_t m63 = sM[63];
        accN[0] = n63; accN[1] = n63;
        accD[0] = m63; accD[1] = m63;
    }

    // Fully unrolled dual Horner: 63 steps x (2 + 2) packed FMAs.
#pragma unroll
    for (int p = 62; p >= 0; p--) {
        uint64_t cn = sN[p];
        uint64_t cm = sM[p];
        accN[0] = fma2(accN[0], xp[0], cn);
        accN[1] = fma2(accN[1], xp[1], cn);
        accD[0] = fma2(accD[0], xp[0], cm);
        accD[1] = fma2(accD[1], xp[1], cm);
    }

    // Epilogue: den = x * Q(x); out = P / (|den| + 1).
    float4 o;
    {
        float nlo, nhi, dlo, dhi, xlo, xhi;
        unpack2(accN[0], nlo, nhi);
        unpack2(accD[0], dlo, dhi);
        unpack2(xp[0],   xlo, xhi);
        o.x = __fdividef(nlo, fabsf(xlo * dlo) + 1.0f);
        o.y = __fdividef(nhi, fabsf(xhi * dhi) + 1.0f);
        unpack2(accN[1], nlo, nhi);
        unpack2(accD[1], dlo, dhi);
        unpack2(xp[1],   xlo, xhi);
        o.z = __fdividef(nlo, fabsf(xlo * dlo) + 1.0f);
        o.w = __fdividef(nhi, fabsf(xhi * dhi) + 1.0f);
    }

    out4[base] = o;
}

extern "C" void kernel_launch(void* const* d_in, const int* in_sizes, int n_in,
                              void* d_out, int out_size) {
    const float* x    = (const float*)d_in[0];
    const float* coef = (const float*)d_in[1];
    float* out        = (float*)d_out;

    int N = in_sizes[0];                 // 4194304, divisible by 1024
    int blocks = N / ELEMS_PER_BLOCK;    // 4096

    rational_kernel<<<blocks, THREADS>>>(
        (const float4*)x, coef, (float4*)out);
}

// round 5
// speedup vs baseline: 1.0763x; 1.0763x over previous
#include <cuda_runtime.h>
#include <cstdint>

// RationalsModel: out[i] = P(x[i]) / (|x[i] * Q(x[i])| + 1)
//   P = sum_{p=0}^{63} coef[p]      * x^p
//   Q = sum_{p=0}^{63} coef[64 + p] * x^p
//
// R5: same theory as R3/R4 (both were broker infra failures), defensively
// simplified: no manual prefetch rotation (ptxas hoists LDS in the unrolled
// body), no min-blocks hint. Core design unchanged:
//  - packed fma.rn.f32x2 (2 scalar FMAs per issue)
//  - coefficients interleaved {dup2(cn), dup2(cm)} -> ONE LDS.128 broadcast
//    per Horner step, amortized over 8 elements (8 FFMA2 = 16 fma-cycles).

__device__ __forceinline__ uint64_t pack2(float lo, float hi) {
    uint64_t r;
    asm("mov.b64 %0, {%1, %2};" : "=l"(r) : "f"(lo), "f"(hi));
    return r;
}

__device__ __forceinline__ void unpack2(uint64_t v, float& lo, float& hi) {
    asm("mov.b64 {%0, %1}, %2;" : "=f"(lo), "=f"(hi) : "l"(v));
}

// d = a * b + c  (packed 2x f32, rt_SMSP=2 for 2 scalar FMAs)
__device__ __forceinline__ uint64_t fma2(uint64_t a, uint64_t b, uint64_t c) {
    uint64_t d;
    asm("fma.rn.f32x2 %0, %1, %2, %3;" : "=l"(d) : "l"(a), "l"(b), "l"(c));
    return d;
}

static constexpr int THREADS = 256;
static constexpr int ELEMS_PER_THREAD = 8;                          // 4 f32x2 lanes
static constexpr int ELEMS_PER_BLOCK = THREADS * ELEMS_PER_THREAD;  // 2048
static constexpr int F4_PER_BLOCK = ELEMS_PER_BLOCK / 4;            // 512

__global__ __launch_bounds__(THREADS)
void rational_kernel(const float4* __restrict__ x4,
                     const float* __restrict__ coef,
                     float4* __restrict__ out4)
{
    // Interleaved coefficient pairs: sC[p] = { dup2(coef[p]), dup2(coef[64+p]) }
    // -> one ld.shared.v2.u64 (LDS.128) broadcast per Horner step.
    __shared__ ulonglong2 sC[64];

    int tid = threadIdx.x;
    if (tid < 64) {
        uint32_t un = __float_as_uint(coef[tid]);
        uint32_t um = __float_as_uint(coef[64 + tid]);
        ulonglong2 v;
        v.x = (uint64_t)un | ((uint64_t)un << 32);
        v.y = (uint64_t)um | ((uint64_t)um << 32);
        sC[tid] = v;
    }
    __syncthreads();

    // Two coalesced float4 loads per thread (stride THREADS apart).
    int base = blockIdx.x * F4_PER_BLOCK + tid;
    float4 a = x4[base];
    float4 b = x4[base + THREADS];

    uint64_t xp[4];
    xp[0] = pack2(a.x, a.y);
    xp[1] = pack2(a.z, a.w);
    xp[2] = pack2(b.x, b.y);
    xp[3] = pack2(b.z, b.w);

    uint64_t accN[4], accD[4];
    {
        ulonglong2 c63 = sC[63];
#pragma unroll
        for (int j = 0; j < 4; j++) { accN[j] = c63.x; accD[j] = c63.y; }
    }

    // Dual Horner, fully unrolled: 63 steps x (4 + 4) packed FMAs,
    // one LDS.128 coefficient broadcast per step.
#pragma unroll
    for (int p = 62; p >= 0; p--) {
        ulonglong2 c = sC[p];
#pragma unroll
        for (int j = 0; j < 4; j++) {
            accN[j] = fma2(accN[j], xp[j], c.x);
            accD[j] = fma2(accD[j], xp[j], c.y);
        }
    }

    // Epilogue: den = x * Q(x); out = P / (|den| + 1).
    float4 o[2];
    float* of = reinterpret_cast<float*>(o);
#pragma unroll
    for (int j = 0; j < 4; j++) {
        float nlo, nhi, dlo, dhi, xlo, xhi;
        unpack2(accN[j], nlo, nhi);
        unpack2(accD[j], dlo, dhi);
        unpack2(xp[j],   xlo, xhi);
        of[2 * j]     = __fdividef(nlo, fabsf(xlo * dlo) + 1.0f);
        of[2 * j + 1] = __fdividef(nhi, fabsf(xhi * dhi) + 1.0f);
    }

    out4[base] = o[0];
    out4[base + THREADS] = o[1];
}

extern "C" void kernel_launch(void* const* d_in, const int* in_sizes, int n_in,
                              void* d_out, int out_size) {
    const float* x    = (const float*)d_in[0];
    const float* coef = (const float*)d_in[1];
    float* out        = (float*)d_out;

    int N = in_sizes[0];                 // 4194304, divisible by 2048
    int blocks = N / ELEMS_PER_BLOCK;    // 2048

    rational_kernel<<<blocks, THREADS>>>(
        (const float4*)x, coef, (float4*)out);
}

// round 6
// speedup vs baseline: 1.0805x; 1.0039x over previous
#include <cuda_runtime.h>
#include <cstdint>

// RationalsModel: out[i] = P(x[i]) / (|x[i] * Q(x[i])| + 1)
//   P = sum_{p=0}^{63} coef[p]      * x^p
//   Q = sum_{p=0}^{63} coef[64 + p] * x^p
//
// R6: R1/R5 showed fma capped at ~63% regardless of LDS instruction count ->
// limiter is per-step LDS latency exposure (29cyc vs 16 fma-cycles/step) plus
// warp convoying at 5 big blocks/SM. Fixes:
//  1) explicit 2-step-deep coefficient prefetch (32 cyc cover >= 29 cyc LDS)
//  2) 128-thread blocks, launch_bounds(128,10) -> 10 blocks/SM (62.5% occ),
//     independently-phased blocks break stall convoys.
// Core unchanged: fma.rn.f32x2, interleaved {dup2(cn),dup2(cm)} LDS.128
// broadcasts, 8 elems/thread.

__device__ __forceinline__ uint64_t pack2(float lo, float hi) {
    uint64_t r;
    asm("mov.b64 %0, {%1, %2};" : "=l"(r) : "f"(lo), "f"(hi));
    return r;
}

__device__ __forceinline__ void unpack2(uint64_t v, float& lo, float& hi) {
    asm("mov.b64 {%0, %1}, %2;" : "=f"(lo), "=f"(hi) : "l"(v));
}

// d = a * b + c  (packed 2x f32, rt_SMSP=2 for 2 scalar FMAs)
__device__ __forceinline__ uint64_t fma2(uint64_t a, uint64_t b, uint64_t c) {
    uint64_t d;
    asm("fma.rn.f32x2 %0, %1, %2, %3;" : "=l"(d) : "l"(a), "l"(b), "l"(c));
    return d;
}

static constexpr int THREADS = 128;
static constexpr int ELEMS_PER_THREAD = 8;                          // 4 f32x2 lanes
static constexpr int ELEMS_PER_BLOCK = THREADS * ELEMS_PER_THREAD;  // 1024
static constexpr int F4_PER_BLOCK = ELEMS_PER_BLOCK / 4;            // 256

__global__ __launch_bounds__(THREADS, 10)
void rational_kernel(const float4* __restrict__ x4,
                     const float* __restrict__ coef,
                     float4* __restrict__ out4)
{
    // Interleaved coefficient pairs: sC[p] = { dup2(coef[p]), dup2(coef[64+p]) }
    // -> one ld.shared.v2.u64 (LDS.128) broadcast per Horner step.
    __shared__ ulonglong2 sC[64];

    int tid = threadIdx.x;
    if (tid < 64) {
        uint32_t un = __float_as_uint(coef[tid]);
        uint32_t um = __float_as_uint(coef[64 + tid]);
        ulonglong2 v;
        v.x = (uint64_t)un | ((uint64_t)un << 32);
        v.y = (uint64_t)um | ((uint64_t)um << 32);
        sC[tid] = v;
    }
    __syncthreads();

    // Two coalesced float4 loads per thread (stride THREADS apart).
    int base = blockIdx.x * F4_PER_BLOCK + tid;
    float4 a = x4[base];
    float4 b = x4[base + THREADS];

    uint64_t xp[4];
    xp[0] = pack2(a.x, a.y);
    xp[1] = pack2(a.z, a.w);
    xp[2] = pack2(b.x, b.y);
    xp[3] = pack2(b.z, b.w);

    uint64_t accN[4], accD[4];
    {
        ulonglong2 c63 = sC[63];
#pragma unroll
        for (int j = 0; j < 4; j++) { accN[j] = c63.x; accD[j] = c63.y; }
    }

    // Dual Horner, fully unrolled, 2-step-deep coefficient prefetch:
    // the LDS for step p issues ~2 steps (32 fma-cycles) before its use.
    ulonglong2 c_cur = sC[62];
    ulonglong2 c_nxt = sC[61];
#pragma unroll
    for (int p = 62; p >= 0; p--) {
        ulonglong2 c_fut;
        if (p >= 2) c_fut = sC[p - 2];
#pragma unroll
        for (int j = 0; j < 4; j++) {
            accN[j] = fma2(accN[j], xp[j], c_cur.x);
            accD[j] = fma2(accD[j], xp[j], c_cur.y);
        }
        c_cur = c_nxt;
        c_nxt = c_fut;
    }

    // Epilogue: den = x * Q(x); out = P / (|den| + 1).
    float4 o[2];
    float* of = reinterpret_cast<float*>(o);
#pragma unroll
    for (int j = 0; j < 4; j++) {
        float nlo, nhi, dlo, dhi, xlo, xhi;
        unpack2(accN[j], nlo, nhi);
        unpack2(accD[j], dlo, dhi);
        unpack2(xp[j],   xlo, xhi);
        of[2 * j]     = __fdividef(nlo, fabsf(xlo * dlo) + 1.0f);
        of[2 * j + 1] = __fdividef(nhi, fabsf(xhi * dhi) + 1.0f);
    }

    out4[base] = o[0];
    out4[base + THREADS] = o[1];
}

extern "C" void kernel_launch(void* const* d_in, const int* in_sizes, int n_in,
                              void* d_out, int out_size) {
    const float* x    = (const float*)d_in[0];
    const float* coef = (const float*)d_in[1];
    float* out        = (float*)d_out;

    int N = in_sizes[0];                 // 4194304, divisible by 1024
    int blocks = N / ELEMS_PER_BLOCK;    // 4096

    rational_kernel<<<blocks, THREADS>>>(
        (const float4*)x, coef, (float4*)out);
}

// round 7
// speedup vs baseline: 1.0862x; 1.0052x over previous
#include <cuda_runtime.h>
#include <cstdint>

// RationalsModel: out[i] = P(x[i]) / (|x[i] * Q(x[i])| + 1)
//   P = sum_{p=0}^{63} coef[p]      * x^p
//   Q = sum_{p=0}^{63} coef[64 + p] * x^p
//
// R7: fma pipe is capped at 2/3 by RF banking: FFMA2 reads 3 register PAIRS
// (3 even + 3 odd distinct regs) -> rt=3 instead of 2. Measured 24.6us ==
// rt3 prediction exactly, invariant across occupancy/LDS variants.
// Fix attempt: move coefficients to __constant__ memory. LDCU loads them into
// UNIFORM registers (separate RF + port); if FFMA2 takes a UR source operand,
// vector-RF reads drop to 2 pairs -> rt=2 -> floor ~14.8us.
// Pipeline: pack kernel (dup2 pairs into __device__ scratch) ->
// cudaMemcpyToSymbolAsync D2D -> main kernel (all graph-capturable).

__device__ __forceinline__ uint64_t pack2(float lo, float hi) {
    uint64_t r;
    asm("mov.b64 %0, {%1, %2};" : "=l"(r) : "f"(lo), "f"(hi));
    return r;
}

__device__ __forceinline__ void unpack2(uint64_t v, float& lo, float& hi) {
    asm("mov.b64 {%0, %1}, %2;" : "=f"(lo), "=f"(hi) : "l"(v));
}

// d = a * b + c  (packed 2x f32)
__device__ __forceinline__ uint64_t fma2(uint64_t a, uint64_t b, uint64_t c) {
    uint64_t d;
    asm("fma.rn.f32x2 %0, %1, %2, %3;" : "=l"(d) : "l"(a), "l"(b), "l"(c));
    return d;
}

// cC[p]    = dup2(coef[p])      (numerator)
// cC[64+p] = dup2(coef[64+p])   (denominator)
__constant__ uint64_t cC[128];
__device__ uint64_t g_pairs[128];

__global__ void pack_kernel(const float* __restrict__ coef) {
    int i = threadIdx.x;  // 128 threads
    uint32_t u = __float_as_uint(coef[i]);
    g_pairs[i] = (uint64_t)u | ((uint64_t)u << 32);
}

static constexpr int THREADS = 128;
static constexpr int ELEMS_PER_THREAD = 8;                          // 4 f32x2 lanes
static constexpr int ELEMS_PER_BLOCK = THREADS * ELEMS_PER_THREAD;  // 1024
static constexpr int F4_PER_BLOCK = ELEMS_PER_BLOCK / 4;            // 256

__global__ __launch_bounds__(THREADS)
void rational_kernel(const float4* __restrict__ x4,
                     float4* __restrict__ out4)
{
    int tid = threadIdx.x;

    // Two coalesced float4 loads per thread (stride THREADS apart).
    int base = blockIdx.x * F4_PER_BLOCK + tid;
    float4 a = x4[base];
    float4 b = x4[base + THREADS];

    uint64_t xp[4];
    xp[0] = pack2(a.x, a.y);
    xp[1] = pack2(a.z, a.w);
    xp[2] = pack2(b.x, b.y);
    xp[3] = pack2(b.z, b.w);

    uint64_t accN[4], accD[4];
    {
        uint64_t n63 = cC[63];
        uint64_t m63 = cC[127];
#pragma unroll
        for (int j = 0; j < 4; j++) { accN[j] = n63; accD[j] = m63; }
    }

    // Dual Horner, fully unrolled. Coefficients come from constant memory
    // with compile-time offsets -> LDCU (uniform-register destination).
#pragma unroll
    for (int p = 62; p >= 0; p--) {
        uint64_t cn = cC[p];
        uint64_t cm = cC[64 + p];
#pragma unroll
        for (int j = 0; j < 4; j++) {
            accN[j] = fma2(accN[j], xp[j], cn);
            accD[j] = fma2(accD[j], xp[j], cm);
        }
    }

    // Epilogue: den = x * Q(x); out = P / (|den| + 1).
    float4 o[2];
    float* of = reinterpret_cast<float*>(o);
#pragma unroll
    for (int j = 0; j < 4; j++) {
        float nlo, nhi, dlo, dhi, xlo, xhi;
        unpack2(accN[j], nlo, nhi);
        unpack2(accD[j], dlo, dhi);
        unpack2(xp[j],   xlo, xhi);
        of[2 * j]     = __fdividef(nlo, fabsf(xlo * dlo) + 1.0f);
        of[2 * j + 1] = __fdividef(nhi, fabsf(xhi * dhi) + 1.0f);
    }

    out4[base] = o[0];
    out4[base + THREADS] = o[1];
}

extern "C" void kernel_launch(void* const* d_in, const int* in_sizes, int n_in,
                              void* d_out, int out_size) {
    const float* x    = (const float*)d_in[0];
    const float* coef = (const float*)d_in[1];
    float* out        = (float*)d_out;

    int N = in_sizes[0];                 // 4194304, divisible by 1024
    int blocks = N / ELEMS_PER_BLOCK;    // 4096

    // 1) Duplicate each coefficient into both halves of a u64 pair.
    pack_kernel<<<1, 128>>>(coef);

    // 2) Stage the packed pairs into constant memory (D2D memcpy node).
    void* src = nullptr;
    cudaGetSymbolAddress(&src, g_pairs);
    cudaMemcpyToSymbolAsync(cC, src, 128 * sizeof(uint64_t), 0,
                            cudaMemcpyDeviceToDevice, 0);

    // 3) Main compute kernel reads coefficients via LDCU.
    rational_kernel<<<blocks, THREADS>>>(
        (const float4*)x, (float4*)out);
}